// round 4
// baseline (speedup 1.0000x reference)
#include <cuda_runtime.h>

// SelfAttentionHead via tf32 mma.sync.
// R4: attn BM=128 full-row warps + double-buffered K/V; GEMM frag-major smem.
// B=16, T=2048, DM=1024, DK=128, fp32 in/out.

#define NB 16
#define T 2048
#define DM 1024
#define DK 128
#define BT (NB * T)

#define QFP 132   // pitch of a fragment row (128 payload floats + 4 pad)
#define KFP 66    // pitch of a float2-frag row (64 payload + 2 pad)

__device__ float g_qkv[3][(size_t)BT * DK];

__device__ __forceinline__ unsigned f2tf(float f) {
    unsigned u; asm("cvt.rna.tf32.f32 %0, %1;" : "=r"(u) : "f"(f)); return u;
}
__device__ __forceinline__ float f2tff(float f) { return __uint_as_float(f2tf(f)); }

#define MMA_TF32(d, a0, a1, a2, a3, b0, b1)                                  \
    asm volatile("mma.sync.aligned.m16n8k8.row.col.f32.tf32.tf32.f32 "       \
                 "{%0,%1,%2,%3}, {%4,%5,%6,%7}, {%8,%9}, {%0,%1,%2,%3};"     \
                 : "+f"(d[0]), "+f"(d[1]), "+f"(d[2]), "+f"(d[3])            \
                 : "r"(a0), "r"(a1), "r"(a2), "r"(a3), "r"(b0), "r"(b1))

// ===========================================================================
// QKV GEMM: out[sel] = x @ W_sel. M=32768, K=1024, N=128. Block 128x128,
// KC=32. 8 warps (4m x 2n), warp tile 32x64. Fragment-major smem:
//   A frag row (mg*4+kc): LDS.128 per frag;  B frag row (ng*4+kc): LDS.64.
// ===========================================================================
#define KC 32

__global__ void __launch_bounds__(256) qkv_gemm_kernel(
    const float* __restrict__ x, const float* __restrict__ Wq,
    const float* __restrict__ Wk, const float* __restrict__ Wv)
{
    __shared__ float Af[32 * QFP];   // 8 mg x 4 kc
    __shared__ float Bf[64 * KFP];   // 16 ng x 4 kc

    const int sel = blockIdx.x;
    const float* W = (sel == 0) ? Wq : (sel == 1 ? Wk : Wv);
    float* outp = g_qkv[sel];
    const int m0 = blockIdx.y * 128;

    const int t = threadIdx.x;
    const int lane = t & 31, wid = t >> 5;
    const int wm = wid >> 1, wn = wid & 1;
    const int lq = lane >> 2, lr = lane & 3;

    const float* xp = x + (size_t)m0 * DM;

    float4 ra[4], rb[4];
    #pragma unroll
    for (int i = 0; i < 4; i++) {
        int f = t + 256 * i;
        ra[i] = *(const float4*)(xp + (size_t)(f >> 3) * DM + 4 * (f & 7));
        rb[i] = *(const float4*)(W + (size_t)(f >> 5) * DK + 4 * (f & 31));
    }

    float c[2][8][4];
    #pragma unroll
    for (int mt = 0; mt < 2; mt++)
        #pragma unroll
        for (int nt = 0; nt < 8; nt++)
            #pragma unroll
            for (int k = 0; k < 4; k++) c[mt][nt][k] = 0.0f;

    for (int k0 = 0; k0 < DM; k0 += KC) {
        __syncthreads();
        #pragma unroll
        for (int i = 0; i < 4; i++) {
            int f = t + 256 * i;
            // A frag store: element (r, c) -> row (mg*4+kc), lane (r&7)*4+(c&3),
            // slot ((r>>3)&1) + 2*((c>>2)&1)
            {
                int r = f >> 3, c4 = f & 7;
                int mg = r >> 4, half = (r >> 3) & 1, lqq = r & 7;
                int kc = c4 >> 1, khalf = c4 & 1;
                float* ap = &Af[(mg * 4 + kc) * QFP + half + 2 * khalf];
                float4 v = ra[i];
                ap[(lqq * 4 + 0) * 4] = f2tff(v.x);
                ap[(lqq * 4 + 1) * 4] = f2tff(v.y);
                ap[(lqq * 4 + 2) * 4] = f2tff(v.z);
                ap[(lqq * 4 + 3) * 4] = f2tff(v.w);
            }
            // B frag store: element (k, n) -> row (ng*4+kc), lane (n&7)*4+(k&3),
            // slot (k>>2)&1
            {
                int k = f >> 5, c4n = f & 31;
                int ng = c4n >> 1, lq0 = 4 * (c4n & 1);
                int kc = k >> 3, s = (k >> 2) & 1, i3 = k & 3;
                float* bp = &Bf[(ng * 4 + kc) * KFP + i3 * 2 + s];
                float4 v = rb[i];
                bp[(lq0 + 0) * 8] = f2tff(v.x);
                bp[(lq0 + 1) * 8] = f2tff(v.y);
                bp[(lq0 + 2) * 8] = f2tff(v.z);
                bp[(lq0 + 3) * 8] = f2tff(v.w);
            }
        }
        __syncthreads();

        if (k0 + KC < DM) {
            #pragma unroll
            for (int i = 0; i < 4; i++) {
                int f = t + 256 * i;
                ra[i] = *(const float4*)(xp + (size_t)(f >> 3) * DM + (k0 + KC) + 4 * (f & 7));
                rb[i] = *(const float4*)(W + (size_t)(k0 + KC + (f >> 5)) * DK + 4 * (f & 31));
            }
        }

        #pragma unroll
        for (int kc = 0; kc < 4; kc++) {
            float4 A0 = *(const float4*)&Af[((2 * wm + 0) * 4 + kc) * QFP + lane * 4];
            float4 A1 = *(const float4*)&Af[((2 * wm + 1) * 4 + kc) * QFP + lane * 4];
            #pragma unroll
            for (int nt = 0; nt < 8; nt++) {
                float2 Bv = *(const float2*)&Bf[((8 * wn + nt) * 4 + kc) * KFP + lane * 2];
                unsigned b0 = __float_as_uint(Bv.x), b1 = __float_as_uint(Bv.y);
                MMA_TF32(c[0][nt], __float_as_uint(A0.x), __float_as_uint(A0.y),
                         __float_as_uint(A0.z), __float_as_uint(A0.w), b0, b1);
                MMA_TF32(c[1][nt], __float_as_uint(A1.x), __float_as_uint(A1.y),
                         __float_as_uint(A1.z), __float_as_uint(A1.w), b0, b1);
            }
        }
    }

    #pragma unroll
    for (int mt = 0; mt < 2; mt++) {
        int row = m0 + wm * 32 + mt * 16 + lq;
        #pragma unroll
        for (int nt = 0; nt < 8; nt++) {
            int col = wn * 64 + nt * 8 + 2 * lr;
            *(float2*)(outp + (size_t)row * DK + col) =
                make_float2(c[mt][nt][0], c[mt][nt][1]);
            *(float2*)(outp + (size_t)(row + 8) * DK + col) =
                make_float2(c[mt][nt][2], c[mt][nt][3]);
        }
    }
}

// ===========================================================================
// Flash attention, BM=128 x BN=64. 8 warps, each owns 16 rows x all 64 cols:
// softmax fully in registers (quad shfl), no cross-warp exchange.
// K/V double-buffered in smem, register-prefetched. 1 sync per iteration.
// ===========================================================================
struct __align__(16) AttnSmem {
    float Qf[128 * QFP];      // [rg*16+kkc][lane*4+slot]
    float Kf[2][128 * KFP];   // [ng*16+kkc][lane*2+slot]
    float Vf[2][128 * KFP];   // [c*16+ng][lane*2+slot]
};
extern __shared__ char attn_raw[];

__device__ __forceinline__ void sts_k(float* Kb, float4 v, int f) {
    int r = f >> 5, c4 = f & 31;
    int ng = r >> 3, lqq = r & 7, kkc = c4 >> 1, s = c4 & 1;
    float* kp = &Kb[(ng * 16 + kkc) * KFP + s];
    kp[(lqq * 4 + 0) * 2] = f2tff(v.x);
    kp[(lqq * 4 + 1) * 2] = f2tff(v.y);
    kp[(lqq * 4 + 2) * 2] = f2tff(v.z);
    kp[(lqq * 4 + 3) * 2] = f2tff(v.w);
}
__device__ __forceinline__ void sts_v(float* Vb, float4 v, int f) {
    int r = f >> 5, c4 = f & 31;
    int kkc = r >> 3, lrr = r & 3, s = (r >> 2) & 1;
    int ng = c4 >> 1, lq0 = 4 * (c4 & 1);
    float* vp = &Vb[(kkc * 16 + ng) * KFP + lrr * 2 + s];
    vp[(lq0 + 0) * 8] = f2tff(v.x);
    vp[(lq0 + 1) * 8] = f2tff(v.y);
    vp[(lq0 + 2) * 8] = f2tff(v.z);
    vp[(lq0 + 3) * 8] = f2tff(v.w);
}

__global__ void __launch_bounds__(256, 1) attn_kernel(float* __restrict__ out)
{
    AttnSmem& sm = *reinterpret_cast<AttnSmem*>(attn_raw);
    const int t = threadIdx.x;
    const int lane = t & 31, wm = t >> 5;      // 8 warps = 8 row groups
    const int lq = lane >> 2, lr = lane & 3;
    const int b = blockIdx.y;
    const int qbi = (int)(gridDim.x - 1) - (int)blockIdx.x;  // long CTAs first
    const int q0 = qbi * 128;

    const float* Q = g_qkv[0] + (size_t)b * T * DK;
    const float* K = g_qkv[1] + (size_t)b * T * DK;
    const float* V = g_qkv[2] + (size_t)b * T * DK;

    // ---- Q -> fragment-major smem (once) ----
    #pragma unroll
    for (int i = 0; i < 16; i++) {
        int f = t + 256 * i;
        int r = f >> 5, c4 = f & 31;
        float4 qv = *(const float4*)(Q + (size_t)(q0 + r) * DK + 4 * c4);
        int rg = r >> 4, lqq = r & 7, half = (r >> 3) & 1;
        int kkc = c4 >> 1, khalf = c4 & 1;
        float* qp = &sm.Qf[(rg * 16 + kkc) * QFP + half + 2 * khalf];
        qp[(lqq * 4 + 0) * 4] = f2tff(qv.x);
        qp[(lqq * 4 + 1) * 4] = f2tff(qv.y);
        qp[(lqq * 4 + 2) * 4] = f2tff(qv.z);
        qp[(lqq * 4 + 3) * 4] = f2tff(qv.w);
    }

    // ---- prologue: tile 0 -> buffer 0 ----
    float4 kreg[8], vreg[8];
    #pragma unroll
    for (int i = 0; i < 8; i++) {
        int f = t + 256 * i;
        int r = f >> 5, c4 = f & 31;
        kreg[i] = *(const float4*)(K + (size_t)r * DK + 4 * c4);
        vreg[i] = *(const float4*)(V + (size_t)r * DK + 4 * c4);
    }
    #pragma unroll
    for (int i = 0; i < 8; i++) {
        sts_k(sm.Kf[0], kreg[i], t + 256 * i);
        sts_v(sm.Vf[0], vreg[i], t + 256 * i);
    }
    __syncthreads();

    const int r1 = 16 * wm + lq;
    float m1 = -1e30f, m2 = -1e30f, l1 = 0.0f, l2 = 0.0f;

    float o[16][4];
    #pragma unroll
    for (int ng = 0; ng < 16; ng++)
        #pragma unroll
        for (int k = 0; k < 4; k++) o[ng][k] = 0.0f;

    const float scale = 0.08838834764831845f;  // 1/sqrt(128)
    const float* qbase = &sm.Qf[(wm * 16) * QFP + lane * 4];
    const int qbend = 2 * qbi + 1;
    int p = 0;

    for (int kb = 0; kb <= qbend; kb++) {
        const int k0 = kb * 64;

        // prefetch next K tile
        if (kb < qbend) {
            #pragma unroll
            for (int i = 0; i < 8; i++) {
                int f = t + 256 * i;
                kreg[i] = *(const float4*)(K + (size_t)(k0 + 64 + (f >> 5)) * DK + 4 * (f & 31));
            }
        }

        // ---- S = Q K^T : warp 16x64 tile ----
        float sc[8][4];
        #pragma unroll
        for (int nt = 0; nt < 8; nt++)
            #pragma unroll
            for (int k = 0; k < 4; k++) sc[nt][k] = 0.0f;

        const float* kfb = &sm.Kf[p][lane * 2];
        #pragma unroll
        for (int kkc = 0; kkc < 16; kkc++) {
            float4 A = *(const float4*)(qbase + kkc * QFP);
            unsigned a0 = __float_as_uint(A.x), a1 = __float_as_uint(A.y);
            unsigned a2 = __float_as_uint(A.z), a3 = __float_as_uint(A.w);
            #pragma unroll
            for (int nt = 0; nt < 8; nt++) {
                float2 Bv = *(const float2*)(kfb + (nt * 16 + kkc) * KFP);
                MMA_TF32(sc[nt], a0, a1, a2, a3,
                         __float_as_uint(Bv.x), __float_as_uint(Bv.y));
            }
        }

        // prefetch next V tile
        if (kb < qbend) {
            #pragma unroll
            for (int i = 0; i < 8; i++) {
                int f = t + 256 * i;
                vreg[i] = *(const float4*)(V + (size_t)(k0 + 64 + (f >> 5)) * DK + 4 * (f & 31));
            }
        }

        // ---- scale + causal mask ----
        if (kb >= 2 * qbi) {
            int gr1 = q0 + r1;
            #pragma unroll
            for (int nt = 0; nt < 8; nt++) {
                int gc = k0 + nt * 8 + 2 * lr;
                sc[nt][0] = (gc     <= gr1)     ? sc[nt][0] * scale : -1e30f;
                sc[nt][1] = (gc + 1 <= gr1)     ? sc[nt][1] * scale : -1e30f;
                sc[nt][2] = (gc     <= gr1 + 8) ? sc[nt][2] * scale : -1e30f;
                sc[nt][3] = (gc + 1 <= gr1 + 8) ? sc[nt][3] * scale : -1e30f;
            }
        } else {
            #pragma unroll
            for (int nt = 0; nt < 8; nt++)
                #pragma unroll
                for (int k = 0; k < 4; k++) sc[nt][k] *= scale;
        }

        // ---- row max (regs + quad shfl) ----
        float mx1 = -1e30f, mx2 = -1e30f;
        #pragma unroll
        for (int nt = 0; nt < 8; nt++) {
            mx1 = fmaxf(mx1, fmaxf(sc[nt][0], sc[nt][1]));
            mx2 = fmaxf(mx2, fmaxf(sc[nt][2], sc[nt][3]));
        }
        mx1 = fmaxf(mx1, __shfl_xor_sync(0xffffffffu, mx1, 1));
        mx1 = fmaxf(mx1, __shfl_xor_sync(0xffffffffu, mx1, 2));
        mx2 = fmaxf(mx2, __shfl_xor_sync(0xffffffffu, mx2, 1));
        mx2 = fmaxf(mx2, __shfl_xor_sync(0xffffffffu, mx2, 2));

        float mn1 = fmaxf(m1, mx1), mn2 = fmaxf(m2, mx2);
        float pc1 = __expf(m1 - mn1), pc2 = __expf(m2 - mn2);
        m1 = mn1; m2 = mn2;

        // ---- exp + row sum ----
        float s1 = 0.0f, s2 = 0.0f;
        #pragma unroll
        for (int nt = 0; nt < 8; nt++) {
            sc[nt][0] = __expf(sc[nt][0] - m1);
            sc[nt][1] = __expf(sc[nt][1] - m1);
            sc[nt][2] = __expf(sc[nt][2] - m2);
            sc[nt][3] = __expf(sc[nt][3] - m2);
            s1 += sc[nt][0] + sc[nt][1];
            s2 += sc[nt][2] + sc[nt][3];
        }
        s1 += __shfl_xor_sync(0xffffffffu, s1, 1);
        s1 += __shfl_xor_sync(0xffffffffu, s1, 2);
        s2 += __shfl_xor_sync(0xffffffffu, s2, 1);
        s2 += __shfl_xor_sync(0xffffffffu, s2, 2);
        l1 = l1 * pc1 + s1;
        l2 = l2 * pc2 + s2;

        // ---- rescale O ----
        #pragma unroll
        for (int ng = 0; ng < 16; ng++) {
            o[ng][0] *= pc1; o[ng][1] *= pc1;
            o[ng][2] *= pc2; o[ng][3] *= pc2;
        }

        // ---- PV: P (shfl-remapped accum -> A frags) x V frags ----
        const float* vfb = &sm.Vf[p][lane * 2];
        const int src1 = (lane & ~3) | (lr >> 1);
        const int src2 = src1 + 2;
        const bool odd = (lr & 1);
        #pragma unroll
        for (int c = 0; c < 8; c++) {
            float p0 = __shfl_sync(0xffffffffu, sc[c][0], src1);
            float p1 = __shfl_sync(0xffffffffu, sc[c][1], src1);
            float p2 = __shfl_sync(0xffffffffu, sc[c][2], src1);
            float p3 = __shfl_sync(0xffffffffu, sc[c][3], src1);
            float u0 = __shfl_sync(0xffffffffu, sc[c][0], src2);
            float u1 = __shfl_sync(0xffffffffu, sc[c][1], src2);
            float u2 = __shfl_sync(0xffffffffu, sc[c][2], src2);
            float u3 = __shfl_sync(0xffffffffu, sc[c][3], src2);
            unsigned a0 = f2tf(odd ? p1 : p0);
            unsigned a1 = f2tf(odd ? p3 : p2);
            unsigned a2 = f2tf(odd ? u1 : u0);
            unsigned a3 = f2tf(odd ? u3 : u2);
            const float* vb = vfb + (c * 16) * KFP;
            #pragma unroll
            for (int ng = 0; ng < 16; ng++) {
                float2 Bv = *(const float2*)(vb + ng * KFP);
                MMA_TF32(o[ng], a0, a1, a2, a3,
                         __float_as_uint(Bv.x), __float_as_uint(Bv.y));
            }
        }

        // ---- stage next tile into the other buffer ----
        if (kb < qbend) {
            #pragma unroll
            for (int i = 0; i < 8; i++) {
                sts_k(sm.Kf[p ^ 1], kreg[i], t + 256 * i);
                sts_v(sm.Vf[p ^ 1], vreg[i], t + 256 * i);
            }
            __syncthreads();
        }
        p ^= 1;
    }

    // ---- epilogue: normalize and store ----
    {
        float inv1 = 1.0f / l1, inv2 = 1.0f / l2;
        float* op = out + ((size_t)b * T + q0) * DK;
        #pragma unroll
        for (int ng = 0; ng < 16; ng++) {
            int cb = ng * 8 + 2 * lr;
            *(float2*)(op + (size_t)r1 * DK + cb) =
                make_float2(o[ng][0] * inv1, o[ng][1] * inv1);
            *(float2*)(op + (size_t)(r1 + 8) * DK + cb) =
                make_float2(o[ng][2] * inv2, o[ng][3] * inv2);
        }
    }
}

// ===========================================================================
extern "C" void kernel_launch(void* const* d_in, const int* in_sizes, int n_in,
                              void* d_out, int out_size)
{
    const float* x  = (const float*)d_in[0];
    const float* Wq = (const float*)d_in[1];
    const float* Wk = (const float*)d_in[2];
    const float* Wv = (const float*)d_in[3];
    float* out = (float*)d_out;

    dim3 g1(3, BT / 128);
    qkv_gemm_kernel<<<g1, 256>>>(x, Wq, Wk, Wv);

    int smem = (int)sizeof(AttnSmem);
    cudaFuncSetAttribute(attn_kernel, cudaFuncAttributeMaxDynamicSharedMemorySize, smem);
    dim3 g2(T / 128, NB);
    attn_kernel<<<g2, 256, (size_t)smem>>>(out);
}